// round 16
// baseline (speedup 1.0000x reference)
#include <cuda_runtime.h>
#include <cstdint>

typedef unsigned long long u64;

#define Bn 64
#define Gn 200
#define QT 5
#define LH 204
#define LQ (8 * LH)
#define HSTR 1002

__device__ float g_Q[Bn * Gn * 128];
__device__ float g_K[Bn * Gn * 128];
__device__ float g_V[Bn * Gn * 128];

__device__ __forceinline__ u64 fma2(u64 a, u64 b, u64 c) {
    u64 d; asm("fma.rn.f32x2 %0, %1, %2, %3;" : "=l"(d) : "l"(a), "l"(b), "l"(c)); return d;
}
__device__ __forceinline__ u64 pk(float lo, float hi) {
    u64 d; asm("mov.b64 %0, {%1, %2};" : "=l"(d) : "f"(lo), "f"(hi)); return d;
}
__device__ __forceinline__ float2 up(u64 a) {
    float2 r; asm("mov.b64 {%0, %1}, %2;" : "=f"(r.x), "=f"(r.y) : "l"(a)); return r;
}
__device__ __forceinline__ float hadd(u64 a) { float2 r = up(a); return r.x + r.y; }
__device__ __forceinline__ u64 relu2(u64 a) {
    float2 v = up(a); return pk(fmaxf(v.x, 0.f), fmaxf(v.y, 0.f));
}
__device__ __forceinline__ uint32_t smem_u32(const void* p) {
    uint32_t a;
    asm("{ .reg .u64 t; cvta.to.shared.u64 t, %1; cvt.u32.u64 %0, t; }" : "=r"(a) : "l"(p));
    return a;
}
__device__ __forceinline__ void mbar_wait0(uint32_t mbar) {
    asm volatile(
        "{\n\t.reg .pred P;\n"
        "W%=: mbarrier.try_wait.parity.shared.b64 P, [%0], 0;\n"
        "@!P bra W%=;\n\t}"
        :: "r"(mbar) : "memory");
}

// ================= kernel 1: QKV proj, g-tile 25, grid 512 (balanced waves) =================
#define SMEM1 ((8192 + 8320) * 4)

__global__ __launch_bounds__(256, 3) void proj_kernel(
    const float* __restrict__ h_em, const float* __restrict__ Wq,
    const float* __restrict__ Wk, const float* __restrict__ Wv)
{
    extern __shared__ float sm1[];
    float* Wsm = sm1;            // [d][o_local 64]
    float* xs  = sm1 + 8192;     // [d][gl] stride 65

    int t  = threadIdx.x;
    int tx = t & 15, ty = t >> 4;
    int g0 = blockIdx.x * 25;
    int b  = blockIdx.y;

    const float4* xsrc = (const float4*)(h_em + (size_t)(b * Gn + g0) * 128);
    for (int i4 = t; i4 < 800; i4 += 256) {
        float4 v = xsrc[i4];
        int gl = i4 >> 5, d4 = (i4 & 31) * 4;
        xs[(d4 + 0) * 65 + gl] = v.x;
        xs[(d4 + 1) * 65 + gl] = v.y;
        xs[(d4 + 2) * 65 + gl] = v.z;
        xs[(d4 + 3) * 65 + gl] = v.w;
    }

    #pragma unroll 1
    for (int w = 0; w < 3; w++) {
        const float* W = (w == 0) ? Wq : (w == 1) ? Wk : Wv;
        float* outp    = (w == 0) ? g_Q : (w == 1) ? g_K : g_V;
        #pragma unroll 1
        for (int wh = 0; wh < 2; wh++) {
            __syncthreads();
            for (int idx = t; idx < 8192; idx += 256) {
                int hl = idx >> 11, d = (idx >> 4) & 127, k = idx & 15;
                Wsm[d * 64 + hl * 16 + k] = W[(wh * 4 + hl) * 2048 + d * 16 + k];
            }
            __syncthreads();

            u64 acc[2][2];
            acc[0][0] = acc[0][1] = acc[1][0] = acc[1][1] = 0ull;

            const u64* Wp = (const u64*)Wsm;
            #pragma unroll 4
            for (int d = 0; d < 128; d++) {
                u64 wv0 = Wp[d * 32 + tx];
                u64 wv1 = Wp[d * 32 + tx + 16];
                #pragma unroll
                for (int i = 0; i < 2; i++) {
                    float x = xs[d * 65 + i * 16 + ty];
                    u64 xv = pk(x, x);
                    acc[i][0] = fma2(xv, wv0, acc[i][0]);
                    acc[i][1] = fma2(xv, wv1, acc[i][1]);
                }
            }
            #pragma unroll
            for (int i = 0; i < 2; i++) {
                int gl = i * 16 + ty;
                if (gl < 25) {
                    float* op = outp + (size_t)(b * Gn + g0 + gl) * 128 + wh * 64 + tx * 2;
                    *(u64*)op        = acc[i][0];
                    *(u64*)(op + 32) = acc[i][1];
                }
            }
        }
    }
}

// ================= kernel 2: fused =================
#define SLAB_BYTES 4000u
#define RSM_F 16032
#define SMEM2 ((RSM_F + 8160 + 640) * 4 + (384 + 128 + 16 + 8 + 8) * 8)

__global__ __launch_bounds__(512, 2) void main_kernel(
    const float* __restrict__ route, const float* __restrict__ W1,
    const float* __restrict__ b1, const float* __restrict__ W2,
    const float* __restrict__ b2, const float* __restrict__ Wo,
    float* __restrict__ out, float* __restrict__ out_route)
{
    extern __shared__ char smraw[];
    float* rsm    = (float*)smraw;            // 16032 f
    float* L      = rsm + RSM_F;              // 8160 f
    float* Qsm    = L + 8160;                 // 640 f (straight layout)
    u64*   W1t    = (u64*)(Qsm + 640);        // 384
    u64*   W2t    = W1t + 384;                // 128
    u64*   b1d    = W2t + 128;                // 16
    u64*   b2d    = b1d + 16;                 // 8
    u64*   mbarp  = b2d + 8;
    float* hidbuf = rsm;
    float* hp     = rsm;
    u64*   headsd = (u64*)(rsm + 3584);
    u64*   scratch= (u64*)(rsm + 3584 + 1280);

    int t  = threadIdx.x;
    int b  = blockIdx.y;
    int q0 = blockIdx.x * QT;
    uint32_t mbar = smem_u32(mbarp);
    uint32_t rsm_a = smem_u32(rsm);

    // ---- phase 0 ----
    const float4* Qs = (const float4*)(g_Q + (size_t)(b * Gn + q0) * 128);
    for (int i4 = t; i4 < 160; i4 += 512) ((float4*)Qsm)[i4] = Qs[i4];
    if (t < 384) {
        int i = t >> 4, j = t & 15;
        float w = W1[j * 24 + i];
        W1t[t] = pk(w, w);
    } else if (t < 512) {
        int idx = t - 384, j = idx >> 3, h = idx & 7;
        float w = W2[h * 16 + j];
        W2t[idx] = pk(w, w);
    }
    if (t < 16)  { b1d[t] = pk(b1[t], b1[t]); }
    if (t >= 16 && t < 24) { int i = t - 16; b2d[i] = pk(b2[i], b2[i]); }
    if (t == 0)
        asm volatile("mbarrier.init.shared.b64 [%0], 1;" :: "r"(mbar) : "memory");
    __syncthreads();

    // ---- kick 16 bulk route loads ----
    if (t == 0) {
        asm volatile("mbarrier.arrive.expect_tx.shared.b64 _, [%0], %1;"
                     :: "r"(mbar), "r"(16u * SLAB_BYTES) : "memory");
        const float* base = route + (size_t)(b * Gn + q0) * Gn;
        #pragma unroll
        for (int r = 0; r < 16; r++) {
            asm volatile(
                "cp.async.bulk.shared::cta.global.mbarrier::complete_tx::bytes [%0], [%1], %2, [%3];"
                :: "r"(rsm_a + r * SLAB_BYTES), "l"(base + (size_t)r * 2560000),
                   "r"(SLAB_BYTES), "r"(mbar) : "memory");
        }
    }

    // ---- phase 1a: h-uniform warps; Q reads are warp-uniform broadcasts ----
    {
        int warp = t >> 5, lane = t & 31;
        int h = warp >> 1, gh = (warp & 1) * 100;
        #pragma unroll 1
        for (int gi = 0; gi < 4; gi++) {
            int g = gh + gi * 32 + lane;
            if (g < gh + 100) {
                const ulonglong2* Kp = (const ulonglong2*)(g_K + (size_t)(b * Gn + g) * 128 + h * 16);
                ulonglong2 kv[4];
                #pragma unroll
                for (int i = 0; i < 4; i++) kv[i] = Kp[i];
                float* Ld = L + h * LH + g;
                #pragma unroll
                for (int q = 0; q < QT; q++) {
                    const ulonglong2* Qr = (const ulonglong2*)(Qsm + q * 128 + h * 16);
                    u64 a = 0ull;
                    #pragma unroll
                    for (int c = 0; c < 4; c++) {
                        ulonglong2 qc = Qr[c];
                        a = fma2(kv[c].x, qc.x, a);
                        a = fma2(kv[c].y, qc.y, a);
                    }
                    Ld[q * LQ] = hadd(a);
                }
            }
        }
    }
    __syncthreads();
    mbar_wait0(mbar);

    // ---- passthrough bulk stores ----
    if (t == 0 && out_route) {
        asm volatile("fence.proxy.async.shared::cta;" ::: "memory");
        float* obase = out_route + (size_t)(b * Gn + q0) * Gn;
        #pragma unroll
        for (int r = 0; r < 16; r++) {
            asm volatile(
                "cp.async.bulk.global.shared::cta.bulk_group [%0], [%1], %2;"
                :: "l"(obase + (size_t)r * 2560000), "r"(rsm_a + r * SLAB_BYTES),
                   "r"(SLAB_BYTES) : "memory");
        }
        asm volatile("cp.async.bulk.commit_group;" ::: "memory");
    }

    // ---- phase 1b layer 1: GEMM, tile 8 pos x 4 j ----
    u64 l1acc[4][4];
    int pt = t >> 2, jg = t & 3;
    int q1 = pt / 25, g1 = (pt - q1 * 25) * 8;
    if (t < 500) {
        #pragma unroll
        for (int j = 0; j < 4; j++) {
            u64 bj = b1d[jg * 4 + j];
            #pragma unroll
            for (int p = 0; p < 4; p++) l1acc[j][p] = bj;
        }
        const ulonglong2* W1t2 = (const ulonglong2*)W1t;
        #pragma unroll
        for (int k = 0; k < 8; k++) {
            const ulonglong2* xp = (const ulonglong2*)(L + q1 * LQ + k * LH + g1);
            ulonglong2 xa = xp[0], xb = xp[1];
            ulonglong2 w01 = W1t2[k * 8 + jg * 2];
            ulonglong2 w23 = W1t2[k * 8 + jg * 2 + 1];
            #pragma unroll
            for (int j = 0; j < 4; j++) {
                u64 w = (j == 0) ? w01.x : (j == 1) ? w01.y : (j == 2) ? w23.x : w23.y;
                l1acc[j][0] = fma2(xa.x, w, l1acc[j][0]);
                l1acc[j][1] = fma2(xa.y, w, l1acc[j][1]);
                l1acc[j][2] = fma2(xb.x, w, l1acc[j][2]);
                l1acc[j][3] = fma2(xb.y, w, l1acc[j][3]);
            }
        }
        #pragma unroll
        for (int r = 0; r < 16; r++) {
            const ulonglong2* xp = (const ulonglong2*)(rsm + r * 1000 + q1 * 200 + g1);
            ulonglong2 xa = xp[0], xb = xp[1];
            ulonglong2 w01 = W1t2[(8 + r) * 8 + jg * 2];
            ulonglong2 w23 = W1t2[(8 + r) * 8 + jg * 2 + 1];
            #pragma unroll
            for (int j = 0; j < 4; j++) {
                u64 w = (j == 0) ? w01.x : (j == 1) ? w01.y : (j == 2) ? w23.x : w23.y;
                l1acc[j][0] = fma2(xa.x, w, l1acc[j][0]);
                l1acc[j][1] = fma2(xa.y, w, l1acc[j][1]);
                l1acc[j][2] = fma2(xb.x, w, l1acc[j][2]);
                l1acc[j][3] = fma2(xb.y, w, l1acc[j][3]);
            }
        }
        #pragma unroll
        for (int j = 0; j < 4; j++)
            #pragma unroll
            for (int p = 0; p < 4; p++) l1acc[j][p] = relu2(l1acc[j][p]);
    }
    if (t == 0 && out_route)
        asm volatile("cp.async.bulk.wait_group 0;" ::: "memory");
    __syncthreads();
    if (t < 500) {
        #pragma unroll
        for (int j = 0; j < 4; j++) {
            u64* hb = (u64*)(hidbuf + (jg * 4 + j) * HSTR + q1 * 200 + g1);
            hb[0] = l1acc[j][0]; hb[1] = l1acc[j][1];
            hb[2] = l1acc[j][2]; hb[3] = l1acc[j][3];
        }
    }
    __syncthreads();

    // ---- phase 1b layer 2: tile 8 pos x 2 h ----
    if (t < 500) {
        int hg = t & 3, h0 = hg * 2;
        u64 a0[4], a1[4];
        #pragma unroll
        for (int p = 0; p < 4; p++) { a0[p] = b2d[h0]; a1[p] = b2d[h0 + 1]; }
        #pragma unroll
        for (int j = 0; j < 16; j++) {
            const u64* hx = (const u64*)(hidbuf + j * HSTR + q1 * 200 + g1);
            u64 x0 = hx[0], x1 = hx[1], x2 = hx[2], x3 = hx[3];
            ulonglong2 w = *(const ulonglong2*)(W2t + j * 8 + h0);
            a0[0] = fma2(x0, w.x, a0[0]); a0[1] = fma2(x1, w.x, a0[1]);
            a0[2] = fma2(x2, w.x, a0[2]); a0[3] = fma2(x3, w.x, a0[3]);
            a1[0] = fma2(x0, w.y, a1[0]); a1[1] = fma2(x1, w.y, a1[1]);
            a1[2] = fma2(x2, w.y, a1[2]); a1[3] = fma2(x3, w.y, a1[3]);
        }
        ulonglong2* d0 = (ulonglong2*)(L + q1 * LQ + h0 * LH + g1);
        ulonglong2* d1 = (ulonglong2*)(L + q1 * LQ + (h0 + 1) * LH + g1);
        ulonglong2 s;
        s.x = a0[0]; s.y = a0[1]; d0[0] = s;
        s.x = a0[2]; s.y = a0[3]; d0[1] = s;
        s.x = a1[0]; s.y = a1[1]; d1[0] = s;
        s.x = a1[2]; s.y = a1[3]; d1[1] = s;
    }
    __syncthreads();

    // ---- phase 2: softmax, float4-vectorized, one warp per (q,h) row ----
    {
        int warp = t >> 5, lane = t & 31;
        for (int row = warp; row < 40; row += 16) {
            float4* Lr = (float4*)(L + (row >> 3) * LQ + (row & 7) * LH);  // 50 float4
            float m = -1e30f;
            for (int i = lane; i < 50; i += 32) {
                float4 v = Lr[i];
                m = fmaxf(m, fmaxf(fmaxf(v.x, v.y), fmaxf(v.z, v.w)));
            }
            #pragma unroll
            for (int o = 16; o > 0; o >>= 1) m = fmaxf(m, __shfl_xor_sync(0xffffffffu, m, o));
            float s = 0.f;
            for (int i = lane; i < 50; i += 32) {
                float4 v = Lr[i];
                v.x = __expf(v.x - m); v.y = __expf(v.y - m);
                v.z = __expf(v.z - m); v.w = __expf(v.w - m);
                Lr[i] = v;
                s += (v.x + v.y) + (v.z + v.w);
            }
            #pragma unroll
            for (int o = 16; o > 0; o >>= 1) s += __shfl_xor_sync(0xffffffffu, s, o);
            float inv = 1.f / s;
            for (int i = lane; i < 50; i += 32) {
                float4 v = Lr[i];
                v.x *= inv; v.y *= inv; v.z *= inv; v.w *= inv;
                Lr[i] = v;
            }
        }
    }
    __syncthreads();

    // ---- phase 3: AV; slices {52,52,48,48} ----
    {
        int s = t >> 7, hv = t & 127, h = hv >> 4;
        int base = s * 48 + ((s < 2) ? s * 4 : 8);
        int len  = (s < 2) ? 52 : 48;
        const float* Vp = g_V + (size_t)(b * Gn + base) * 128 + hv;
        const float* Lh = L + h * LH + base;
        u64 acc[QT];
        #pragma unroll
        for (int q = 0; q < QT; q++) acc[q] = 0ull;
        for (int i = 0; i < len; i += 4) {
            float v0 = Vp[(i + 0) * 128], v1 = Vp[(i + 1) * 128];
            float v2 = Vp[(i + 2) * 128], v3 = Vp[(i + 3) * 128];
            u64 va = pk(v0, v1), vb = pk(v2, v3);
            #pragma unroll
            for (int q = 0; q < QT; q++) {
                ulonglong2 p = *(const ulonglong2*)(Lh + q * LQ + i);
                acc[q] = fma2(p.x, va, acc[q]);
                acc[q] = fma2(p.y, vb, acc[q]);
            }
        }
        float* hpd = hp + (s * 128 + hv) * 7;
        #pragma unroll
        for (int q = 0; q < QT; q++) hpd[q] = hadd(acc[q]);
    }
    __syncthreads();
    if (t < 128) {
        #pragma unroll
        for (int q = 0; q < QT; q++) {
            float v = hp[t * 7 + q] + hp[(128 + t) * 7 + q]
                    + hp[(256 + t) * 7 + q] + hp[(384 + t) * 7 + q];
            headsd[q * 128 + t] = pk(v, v);
        }
    }
    __syncthreads();

    // ---- epilogue ----
    if (t < 128) {
        int half = t >> 6, ep = t & 63;
        const u64* Wop = (const u64*)Wo + ep;
        u64 acc[QT];
        #pragma unroll
        for (int q = 0; q < QT; q++) acc[q] = 0ull;
        int hv0 = half * 64;
        for (int hv = hv0; hv < hv0 + 64; hv += 2) {
            u64 w0 = Wop[hv * 64];
            u64 w1 = Wop[(hv + 1) * 64];
            #pragma unroll
            for (int q = 0; q < QT; q++) {
                ulonglong2 hh = *(const ulonglong2*)(headsd + q * 128 + hv);
                acc[q] = fma2(hh.x, w0, acc[q]);
                acc[q] = fma2(hh.y, w1, acc[q]);
            }
        }
        #pragma unroll
        for (int q = 0; q < QT; q++) scratch[t * QT + q] = acc[q];
    }
    __syncthreads();
    if (t < 64) {
        #pragma unroll
        for (int q = 0; q < QT; q++) {
            float2 a = up(scratch[t * QT + q]);
            float2 c = up(scratch[(64 + t) * QT + q]);
            float2 r; r.x = a.x + c.x; r.y = a.y + c.y;
            *(float2*)(out + (size_t)(b * Gn + q0 + q) * 128 + t * 2) = r;
        }
    }
}

extern "C" void kernel_launch(void* const* d_in, const int* in_sizes, int n_in,
                              void* d_out, int out_size) {
    const float* h_em  = (const float*)d_in[0];
    const float* route = (const float*)d_in[1];
    const float* Wq    = (const float*)d_in[2];
    const float* Wk    = (const float*)d_in[3];
    const float* Wv    = (const float*)d_in[4];
    const float* W1    = (const float*)d_in[5];
    const float* b1    = (const float*)d_in[6];
    const float* W2    = (const float*)d_in[7];
    const float* b2    = (const float*)d_in[8];
    const float* Wo    = (const float*)d_in[9];
    float* out = (float*)d_out;

    float* out_route = nullptr;
    if (out_size >= 1638400 + 40960000) out_route = out + 1638400;

    static bool attr_done = false;
    if (!attr_done) {
        cudaFuncSetAttribute(proj_kernel, cudaFuncAttributeMaxDynamicSharedMemorySize, SMEM1);
        cudaFuncSetAttribute(main_kernel, cudaFuncAttributeMaxDynamicSharedMemorySize, SMEM2);
        attr_done = true;
    }

    dim3 grid1(8, Bn);
    proj_kernel<<<grid1, 256, SMEM1>>>(h_em, Wq, Wk, Wv);
    dim3 grid2(Gn / QT, Bn);
    main_kernel<<<grid2, 512, SMEM2>>>(route, W1, b1, W2, b2, Wo, out, out_route);
}

// round 17
// speedup vs baseline: 1.2645x; 1.2645x over previous
#include <cuda_runtime.h>
#include <cstdint>

typedef unsigned long long u64;

#define Bn 64
#define Gn 200
#define QT 5
#define LH 204
#define LQ (8 * LH)
#define HSTR 1002

__device__ float g_Q[Bn * Gn * 128];
__device__ float g_Kt[Bn * 8 * 16 * Gn];   // [b][h][k][g]
__device__ float g_V[Bn * Gn * 128];

__device__ __forceinline__ u64 fma2(u64 a, u64 b, u64 c) {
    u64 d; asm("fma.rn.f32x2 %0, %1, %2, %3;" : "=l"(d) : "l"(a), "l"(b), "l"(c)); return d;
}
__device__ __forceinline__ u64 pk(float lo, float hi) {
    u64 d; asm("mov.b64 %0, {%1, %2};" : "=l"(d) : "f"(lo), "f"(hi)); return d;
}
__device__ __forceinline__ float2 up(u64 a) {
    float2 r; asm("mov.b64 {%0, %1}, %2;" : "=f"(r.x), "=f"(r.y) : "l"(a)); return r;
}
__device__ __forceinline__ float hadd(u64 a) { float2 r = up(a); return r.x + r.y; }
__device__ __forceinline__ u64 relu2(u64 a) {
    float2 v = up(a); return pk(fmaxf(v.x, 0.f), fmaxf(v.y, 0.f));
}
__device__ __forceinline__ uint32_t smem_u32(const void* p) {
    uint32_t a;
    asm("{ .reg .u64 t; cvta.to.shared.u64 t, %1; cvt.u32.u64 %0, t; }" : "=r"(a) : "l"(p));
    return a;
}
__device__ __forceinline__ void mbar_wait0(uint32_t mbar) {
    asm volatile(
        "{\n\t.reg .pred P;\n"
        "W%=: mbarrier.try_wait.parity.shared.b64 P, [%0], 0;\n"
        "@!P bra W%=;\n\t}"
        :: "r"(mbar) : "memory");
}

// ================= kernel 1: QKV proj (R5 form: grid (4,Bn,3)); K written transposed =================
#define SMEM1 ((8192 + 8320) * 4)

__global__ __launch_bounds__(256, 3) void proj_kernel(
    const float* __restrict__ h_em, const float* __restrict__ Wq,
    const float* __restrict__ Wk, const float* __restrict__ Wv)
{
    extern __shared__ float sm1[];
    float* Wsm = sm1;            // [d][o_local 64]
    float* xs  = sm1 + 8192;     // [d][gl] stride 65

    int t  = threadIdx.x;
    int tx = t & 15, ty = t >> 4;
    int g0 = blockIdx.x * 50;
    int b  = blockIdx.y;
    int w  = blockIdx.z;
    const float* W = (w == 0) ? Wq : (w == 1) ? Wk : Wv;

    const float4* xsrc = (const float4*)(h_em + (size_t)(b * Gn + g0) * 128);
    for (int i4 = t; i4 < 1600; i4 += 256) {
        float4 v = xsrc[i4];
        int gl = i4 >> 5, d4 = (i4 & 31) * 4;
        xs[(d4 + 0) * 65 + gl] = v.x;
        xs[(d4 + 1) * 65 + gl] = v.y;
        xs[(d4 + 2) * 65 + gl] = v.z;
        xs[(d4 + 3) * 65 + gl] = v.w;
    }

    #pragma unroll 1
    for (int wh = 0; wh < 2; wh++) {
        __syncthreads();
        for (int idx = t; idx < 8192; idx += 256) {
            int hl = idx >> 11, d = (idx >> 4) & 127, k = idx & 15;
            Wsm[d * 64 + hl * 16 + k] = W[(wh * 4 + hl) * 2048 + d * 16 + k];
        }
        __syncthreads();

        u64 acc[4][2];
        #pragma unroll
        for (int i = 0; i < 4; i++) { acc[i][0] = 0ull; acc[i][1] = 0ull; }

        const u64* Wp = (const u64*)Wsm;
        #pragma unroll 4
        for (int d = 0; d < 128; d++) {
            u64 wv0 = Wp[d * 32 + tx];
            u64 wv1 = Wp[d * 32 + tx + 16];
            #pragma unroll
            for (int i = 0; i < 4; i++) {
                float x = xs[d * 65 + i * 16 + ty];
                u64 xv = pk(x, x);
                acc[i][0] = fma2(xv, wv0, acc[i][0]);
                acc[i][1] = fma2(xv, wv1, acc[i][1]);
            }
        }
        #pragma unroll
        for (int i = 0; i < 4; i++) {
            int gl = i * 16 + ty;
            if (gl < 50) {
                int g = g0 + gl;
                if (w == 1) {
                    // transposed K: g_Kt[b][h][k][g]
                    #pragma unroll
                    for (int j = 0; j < 2; j++) {
                        int o = wh * 64 + tx * 2 + j * 32;
                        int h = o >> 4, k = o & 15;
                        float2 r = up(acc[i][j]);
                        size_t base = ((size_t)(b * 8 + h) * 16 + k) * Gn + g;
                        g_Kt[base]      = r.x;
                        g_Kt[base + Gn] = r.y;
                    }
                } else {
                    float* outp = (w == 0) ? g_Q : g_V;
                    float* op = outp + (size_t)(b * Gn + g) * 128 + wh * 64 + tx * 2;
                    *(u64*)op        = acc[i][0];
                    *(u64*)(op + 32) = acc[i][1];
                }
            }
        }
    }
}

// ================= kernel 2: fused =================
#define SLAB_BYTES 4000u
#define RSM_F 16032
#define SMEM2 ((RSM_F + 8160 + 640) * 4 + (384 + 128 + 16 + 8 + 8) * 8)

__global__ __launch_bounds__(512, 2) void main_kernel(
    const float* __restrict__ route, const float* __restrict__ W1,
    const float* __restrict__ b1, const float* __restrict__ W2,
    const float* __restrict__ b2, const float* __restrict__ Wo,
    float* __restrict__ out, float* __restrict__ out_route)
{
    extern __shared__ char smraw[];
    float* rsm    = (float*)smraw;            // 16032 f
    float* L      = rsm + RSM_F;              // 8160 f
    float* Qsm    = L + 8160;                 // 640 f (straight)
    u64*   W1t    = (u64*)(Qsm + 640);        // 384
    u64*   W2t    = W1t + 384;                // 128
    u64*   b1d    = W2t + 128;                // 16
    u64*   b2d    = b1d + 16;                 // 8
    u64*   mbarp  = b2d + 8;
    float* hidbuf = rsm;
    float* hp     = rsm;
    u64*   headsd = (u64*)(rsm + 3584);
    u64*   scratch= (u64*)(rsm + 3584 + 1280);

    int t  = threadIdx.x;
    int b  = blockIdx.y;
    int q0 = blockIdx.x * QT;
    uint32_t mbar = smem_u32(mbarp);
    uint32_t rsm_a = smem_u32(rsm);

    // ---- phase 0 ----
    const float4* Qs = (const float4*)(g_Q + (size_t)(b * Gn + q0) * 128);
    for (int i4 = t; i4 < 160; i4 += 512) ((float4*)Qsm)[i4] = Qs[i4];
    if (t < 384) {
        int i = t >> 4, j = t & 15;
        float w = W1[j * 24 + i];
        W1t[t] = pk(w, w);
    } else if (t < 512) {
        int idx = t - 384, j = idx >> 3, h = idx & 7;
        float w = W2[h * 16 + j];
        W2t[idx] = pk(w, w);
    }
    if (t < 16)  { b1d[t] = pk(b1[t], b1[t]); }
    if (t >= 16 && t < 24) { int i = t - 16; b2d[i] = pk(b2[i], b2[i]); }
    if (t == 0)
        asm volatile("mbarrier.init.shared.b64 [%0], 1;" :: "r"(mbar) : "memory");
    __syncthreads();

    // ---- kick 16 bulk route loads ----
    if (t == 0) {
        asm volatile("mbarrier.arrive.expect_tx.shared.b64 _, [%0], %1;"
                     :: "r"(mbar), "r"(16u * SLAB_BYTES) : "memory");
        const float* base = route + (size_t)(b * Gn + q0) * Gn;
        #pragma unroll
        for (int r = 0; r < 16; r++) {
            asm volatile(
                "cp.async.bulk.shared::cta.global.mbarrier::complete_tx::bytes [%0], [%1], %2, [%3];"
                :: "r"(rsm_a + r * SLAB_BYTES), "l"(base + (size_t)r * 2560000),
                   "r"(SLAB_BYTES), "r"(mbar) : "memory");
        }
    }

    // ---- phase 1a: qk via transposed K. warp=(h,half); lane=g-pair; coalesced u64 K loads ----
    {
        int warp = t >> 5, lane = t & 31;
        int h = warp >> 1, gbase = (warp & 1) * 100;
        const float* Kb = g_Kt + ((size_t)(b * 8 + h) * 16) * Gn;
        #pragma unroll 1
        for (int it = 0; it < 2; it++) {
            int p = it * 32 + lane;
            if (p < 50) {
                int g = gbase + p * 2;
                u64 kv[16];
                #pragma unroll
                for (int k = 0; k < 16; k++)
                    kv[k] = *(const u64*)(Kb + k * Gn + g);
                #pragma unroll
                for (int q = 0; q < QT; q++) {
                    const float* Qr = Qsm + q * 128 + h * 16;
                    u64 a = 0ull;
                    #pragma unroll
                    for (int k = 0; k < 16; k++) {
                        float qs = Qr[k];
                        a = fma2(kv[k], pk(qs, qs), a);
                    }
                    *(u64*)(L + q * LQ + h * LH + g) = a;
                }
            }
        }
    }
    __syncthreads();
    mbar_wait0(mbar);

    // ---- passthrough bulk stores ----
    if (t == 0 && out_route) {
        asm volatile("fence.proxy.async.shared::cta;" ::: "memory");
        float* obase = out_route + (size_t)(b * Gn + q0) * Gn;
        #pragma unroll
        for (int r = 0; r < 16; r++) {
            asm volatile(
                "cp.async.bulk.global.shared::cta.bulk_group [%0], [%1], %2;"
                :: "l"(obase + (size_t)r * 2560000), "r"(rsm_a + r * SLAB_BYTES),
                   "r"(SLAB_BYTES) : "memory");
        }
        asm volatile("cp.async.bulk.commit_group;" ::: "memory");
    }

    // ---- phase 1b layer 1: GEMM, tile 8 pos x 4 j ----
    u64 l1acc[4][4];
    int pt = t >> 2, jg = t & 3;
    int q1 = pt / 25, g1 = (pt - q1 * 25) * 8;
    if (t < 500) {
        #pragma unroll
        for (int j = 0; j < 4; j++) {
            u64 bj = b1d[jg * 4 + j];
            #pragma unroll
            for (int p = 0; p < 4; p++) l1acc[j][p] = bj;
        }
        const ulonglong2* W1t2 = (const ulonglong2*)W1t;
        #pragma unroll
        for (int k = 0; k < 8; k++) {
            const ulonglong2* xp = (const ulonglong2*)(L + q1 * LQ + k * LH + g1);
            ulonglong2 xa = xp[0], xb = xp[1];
            ulonglong2 w01 = W1t2[k * 8 + jg * 2];
            ulonglong2 w23 = W1t2[k * 8 + jg * 2 + 1];
            #pragma unroll
            for (int j = 0; j < 4; j++) {
                u64 w = (j == 0) ? w01.x : (j == 1) ? w01.y : (j == 2) ? w23.x : w23.y;
                l1acc[j][0] = fma2(xa.x, w, l1acc[j][0]);
                l1acc[j][1] = fma2(xa.y, w, l1acc[j][1]);
                l1acc[j][2] = fma2(xb.x, w, l1acc[j][2]);
                l1acc[j][3] = fma2(xb.y, w, l1acc[j][3]);
            }
        }
        #pragma unroll
        for (int r = 0; r < 16; r++) {
            const ulonglong2* xp = (const ulonglong2*)(rsm + r * 1000 + q1 * 200 + g1);
            ulonglong2 xa = xp[0], xb = xp[1];
            ulonglong2 w01 = W1t2[(8 + r) * 8 + jg * 2];
            ulonglong2 w23 = W1t2[(8 + r) * 8 + jg * 2 + 1];
            #pragma unroll
            for (int j = 0; j < 4; j++) {
                u64 w = (j == 0) ? w01.x : (j == 1) ? w01.y : (j == 2) ? w23.x : w23.y;
                l1acc[j][0] = fma2(xa.x, w, l1acc[j][0]);
                l1acc[j][1] = fma2(xa.y, w, l1acc[j][1]);
                l1acc[j][2] = fma2(xb.x, w, l1acc[j][2]);
                l1acc[j][3] = fma2(xb.y, w, l1acc[j][3]);
            }
        }
        #pragma unroll
        for (int j = 0; j < 4; j++)
            #pragma unroll
            for (int p = 0; p < 4; p++) l1acc[j][p] = relu2(l1acc[j][p]);
    }
    if (t == 0 && out_route)
        asm volatile("cp.async.bulk.wait_group 0;" ::: "memory");
    __syncthreads();
    if (t < 500) {
        #pragma unroll
        for (int j = 0; j < 4; j++) {
            u64* hb = (u64*)(hidbuf + (jg * 4 + j) * HSTR + q1 * 200 + g1);
            hb[0] = l1acc[j][0]; hb[1] = l1acc[j][1];
            hb[2] = l1acc[j][2]; hb[3] = l1acc[j][3];
        }
    }
    __syncthreads();

    // ---- phase 1b layer 2: tile 8 pos x 2 h ----
    if (t < 500) {
        int hg = t & 3, h0 = hg * 2;
        u64 a0[4], a1[4];
        #pragma unroll
        for (int p = 0; p < 4; p++) { a0[p] = b2d[h0]; a1[p] = b2d[h0 + 1]; }
        #pragma unroll
        for (int j = 0; j < 16; j++) {
            const u64* hx = (const u64*)(hidbuf + j * HSTR + q1 * 200 + g1);
            u64 x0 = hx[0], x1 = hx[1], x2 = hx[2], x3 = hx[3];
            ulonglong2 w = *(const ulonglong2*)(W2t + j * 8 + h0);
            a0[0] = fma2(x0, w.x, a0[0]); a0[1] = fma2(x1, w.x, a0[1]);
            a0[2] = fma2(x2, w.x, a0[2]); a0[3] = fma2(x3, w.x, a0[3]);
            a1[0] = fma2(x0, w.y, a1[0]); a1[1] = fma2(x1, w.y, a1[1]);
            a1[2] = fma2(x2, w.y, a1[2]); a1[3] = fma2(x3, w.y, a1[3]);
        }
        ulonglong2* d0 = (ulonglong2*)(L + q1 * LQ + h0 * LH + g1);
        ulonglong2* d1 = (ulonglong2*)(L + q1 * LQ + (h0 + 1) * LH + g1);
        ulonglong2 s;
        s.x = a0[0]; s.y = a0[1]; d0[0] = s;
        s.x = a0[2]; s.y = a0[3]; d0[1] = s;
        s.x = a1[0]; s.y = a1[1]; d1[0] = s;
        s.x = a1[2]; s.y = a1[3]; d1[1] = s;
    }
    __syncthreads();

    // ---- phase 2: softmax, float4-vectorized ----
    {
        int warp = t >> 5, lane = t & 31;
        for (int row = warp; row < 40; row += 16) {
            float4* Lr = (float4*)(L + (row >> 3) * LQ + (row & 7) * LH);
            float m = -1e30f;
            for (int i = lane; i < 50; i += 32) {
                float4 v = Lr[i];
                m = fmaxf(m, fmaxf(fmaxf(v.x, v.y), fmaxf(v.z, v.w)));
            }
            #pragma unroll
            for (int o = 16; o > 0; o >>= 1) m = fmaxf(m, __shfl_xor_sync(0xffffffffu, m, o));
            float s = 0.f;
            for (int i = lane; i < 50; i += 32) {
                float4 v = Lr[i];
                v.x = __expf(v.x - m); v.y = __expf(v.y - m);
                v.z = __expf(v.z - m); v.w = __expf(v.w - m);
                Lr[i] = v;
                s += (v.x + v.y) + (v.z + v.w);
            }
            #pragma unroll
            for (int o = 16; o > 0; o >>= 1) s += __shfl_xor_sync(0xffffffffu, s, o);
            float inv = 1.f / s;
            for (int i = lane; i < 50; i += 32) {
                float4 v = Lr[i];
                v.x *= inv; v.y *= inv; v.z *= inv; v.w *= inv;
                Lr[i] = v;
            }
        }
    }
    __syncthreads();

    // ---- phase 3: AV; slices {52,52,48,48} ----
    {
        int s = t >> 7, hv = t & 127, h = hv >> 4;
        int base = s * 48 + ((s < 2) ? s * 4 : 8);
        int len  = (s < 2) ? 52 : 48;
        const float* Vp = g_V + (size_t)(b * Gn + base) * 128 + hv;
        const float* Lh = L + h * LH + base;
        u64 acc[QT];
        #pragma unroll
        for (int q = 0; q < QT; q++) acc[q] = 0ull;
        for (int i = 0; i < len; i += 4) {
            float v0 = Vp[(i + 0) * 128], v1 = Vp[(i + 1) * 128];
            float v2 = Vp[(i + 2) * 128], v3 = Vp[(i + 3) * 128];
            u64 va = pk(v0, v1), vb = pk(v2, v3);
            #pragma unroll
            for (int q = 0; q < QT; q++) {
                ulonglong2 p = *(const ulonglong2*)(Lh + q * LQ + i);
                acc[q] = fma2(p.x, va, acc[q]);
                acc[q] = fma2(p.y, vb, acc[q]);
            }
        }
        float* hpd = hp + (s * 128 + hv) * 7;
        #pragma unroll
        for (int q = 0; q < QT; q++) hpd[q] = hadd(acc[q]);
    }
    __syncthreads();
    if (t < 128) {
        #pragma unroll
        for (int q = 0; q < QT; q++) {
            float v = hp[t * 7 + q] + hp[(128 + t) * 7 + q]
                    + hp[(256 + t) * 7 + q] + hp[(384 + t) * 7 + q];
            headsd[q * 128 + t] = pk(v, v);
        }
    }
    __syncthreads();

    // ---- epilogue ----
    if (t < 128) {
        int half = t >> 6, ep = t & 63;
        const u64* Wop = (const u64*)Wo + ep;
        u64 acc[QT];
        #pragma unroll
        for (int q = 0; q < QT; q++) acc[q] = 0ull;
        int hv0 = half * 64;
        for (int hv = hv0; hv < hv0 + 64; hv += 2) {
            u64 w0 = Wop[hv * 64];
            u64 w1 = Wop[(hv + 1) * 64];
            #pragma unroll
            for (int q = 0; q < QT; q++) {
                ulonglong2 hh = *(const ulonglong2*)(headsd + q * 128 + hv);
                acc[q] = fma2(hh.x, w0, acc[q]);
                acc[q] = fma2(hh.y, w1, acc[q]);
            }
        }
        #pragma unroll
        for (int q = 0; q < QT; q++) scratch[t * QT + q] = acc[q];
    }
    __syncthreads();
    if (t < 64) {
        #pragma unroll
        for (int q = 0; q < QT; q++) {
            float2 a = up(scratch[t * QT + q]);
            float2 c = up(scratch[(64 + t) * QT + q]);
            float2 r; r.x = a.x + c.x; r.y = a.y + c.y;
            *(float2*)(out + (size_t)(b * Gn + q0 + q) * 128 + t * 2) = r;
        }
    }
}

extern "C" void kernel_launch(void* const* d_in, const int* in_sizes, int n_in,
                              void* d_out, int out_size) {
    const float* h_em  = (const float*)d_in[0];
    const float* route = (const float*)d_in[1];
    const float* Wq    = (const float*)d_in[2];
    const float* Wk    = (const float*)d_in[3];
    const float* Wv    = (const float*)d_in[4];
    const float* W1    = (const float*)d_in[5];
    const float* b1    = (const float*)d_in[6];
    const float* W2    = (const float*)d_in[7];
    const float* b2    = (const float*)d_in[8];
    const float* Wo    = (const float*)d_in[9];
    float* out = (float*)d_out;

    float* out_route = nullptr;
    if (out_size >= 1638400 + 40960000) out_route = out + 1638400;

    static bool attr_done = false;
    if (!attr_done) {
        cudaFuncSetAttribute(proj_kernel, cudaFuncAttributeMaxDynamicSharedMemorySize, SMEM1);
        cudaFuncSetAttribute(main_kernel, cudaFuncAttributeMaxDynamicSharedMemorySize, SMEM2);
        attr_done = true;
    }

    dim3 grid1(4, Bn, 3);
    proj_kernel<<<grid1, 256, SMEM1>>>(h_em, Wq, Wk, Wv);
    dim3 grid2(Gn / QT, Bn);
    main_kernel<<<grid2, 512, SMEM2>>>(route, W1, b1, W2, b2, Wo, out, out_route);
}